// round 16
// baseline (speedup 1.0000x reference)
#include <cuda_runtime.h>
#include <cuda_fp16.h>
#include <math.h>
#include <stdint.h>

#define N_NODES 8192
#define D 64
#define NT 8192
#define EMAX 262144
#define BB 512            // fused-kernel blocks (all resident: 4/SM x 148 = 592)
#define BT 512            // fused-kernel threads

// ---------------- scratch (no allocations allowed) ----------------
// Invariant: g_deg, g_scan_done, g_csr_done are ZERO at entry (zero-init at
// load; re-zeroed by the GEMM's idle lower-triangle CTAs every call).
__device__ float g_deg[N_NODES];
__device__ float g_dinv[N_NODES];
__device__ int   g_off[N_NODES];
__device__ int   g_cur[N_NODES];
__device__ int   g_csr[EMAX];
__device__ float g_h[N_NODES * D];     // x @ W
__device__ __half g_P[N_NODES * D];    // fp16(relu(gcn)) — both GEMM operands
__device__ volatile int g_scan_done;
__device__ int   g_csr_done;

struct Cls {
    const float* x;
    const void*  ei;
    const float* W;
    const float* b;
    int E;
    int ei32;
};

__device__ const float* gp_x;
__device__ const void*  gp_ei;
__device__ const float* gp_W;
__device__ const float* gp_b;
__device__ int          g_E;
__device__ int          g_ei32;

__device__ __forceinline__ bool rok64(const long long* p, int n) {
    int st = n >> 3;
    long long v[8];
#pragma unroll
    for (int k = 0; k < 8; k++) v[k] = p[k * st];
    bool ok = true;
#pragma unroll
    for (int k = 0; k < 8; k++) ok &= (v[k] >= 0 && v[k] < N_NODES);
    return ok;
}
__device__ __forceinline__ bool rok32(const int* p, int n) {
    int st = n >> 3;
    int v[8];
#pragma unroll
    for (int k = 0; k < 8; k++) v[k] = p[k * st];
    bool ok = true;
#pragma unroll
    for (int k = 0; k < 8; k++) ok &= (v[k] >= 0 && v[k] < N_NODES);
    return ok;
}

__device__ Cls do_classify(const void* p0, const void* p1, const void* p2, const void* p3,
                           int s0, int s1, int s2, int s3) {
    Cls c; c.x = nullptr; c.ei = nullptr; c.W = nullptr; c.b = nullptr; c.E = 0; c.ei32 = 1;
    const void* ps[4] = {p0, p1, p2, p3};
    int ss[4] = {s0, s1, s2, s3};
    int big[2]; int nb = 0;
#pragma unroll
    for (int j = 0; j < 4; j++) {
        if (ss[j] == D) c.b = (const float*)ps[j];
        else if (ss[j] == D * D) c.W = (const float*)ps[j];
        else if (nb < 2) big[nb++] = j;
    }
#pragma unroll
    for (int k = 0; k < 2; k++) {
        const void* cand = ps[big[k]];
        int n = ss[big[k]];
        const void* other = ps[big[1 - k]];
        if (rok64((const long long*)cand, n)) {
            c.ei = cand; c.ei32 = 0; c.E = n / 2; c.x = (const float*)other; return c;
        }
        if (rok32((const int*)cand, n)) {
            c.ei = cand; c.ei32 = 1; c.E = n / 2; c.x = (const float*)other; return c;
        }
    }
    c.ei = ps[big[1]]; c.ei32 = 1; c.E = ss[big[1]] / 2;
    c.x = (const float*)ps[big[0]];
    return c;
}

__device__ __forceinline__ int fetch_idx(const void* ei, int i, int ei32) {
    if (ei32) return ((const int*)ei)[i];
    return (int)((const long long*)ei)[i];
}

__device__ __forceinline__ uint32_t smem_u32(const void* p) {
    uint32_t a;
    asm("{ .reg .u64 t; cvta.to.shared.u64 t, %1; cvt.u32.u64 %0, t; }" : "=r"(a) : "l"(p));
    return a;
}

// ---- launch 0: classify+publish, deg histogram (blocks 0..1023), x@W (1024..2047) ----
__global__ void k_deg_xw(const void* p0, const void* p1, const void* p2, const void* p3,
                         int s0, int s1, int s2, int s3) {
    Cls c = do_classify(p0, p1, p2, p3, s0, s1, s2, s3);
    int blk = blockIdx.x, tid = threadIdx.x;
    if (blk == 0 && tid == 0) {
        gp_x = c.x; gp_ei = c.ei; gp_W = c.W; gp_b = c.b; g_E = c.E; g_ei32 = c.ei32;
        __threadfence();
    }
    if (blk < 1024) {
        int e = blk * 256 + tid;
        if (e < c.E && e < EMAX) {
            int dst = fetch_idx(c.ei, c.E + e, c.ei32);
            if ((unsigned)dst < (unsigned)N_NODES) atomicAdd(&g_deg[dst], 1.0f);
        }
        return;
    }
    // x @ W: 1024 blocks x 8 rows, x staged in smem, 2 outputs/thread
    __shared__ float sW[D * D];
    __shared__ float sx[8 * D];
    int base = (blk - 1024) * 8;
#pragma unroll
    for (int i = 0; i < 4; i++)
        ((float4*)sW)[tid + i * 256] = ((const float4*)c.W)[tid + i * 256];
    if (tid < 128)
        ((float4*)sx)[tid] = ((const float4*)(c.x + base * D))[tid];
    __syncthreads();
    int col = tid & 63, rg = tid >> 6;
    float acc0 = 0.0f, acc1 = 0.0f;
#pragma unroll
    for (int k = 0; k < D; k++) {
        float w = sW[k * D + col];
        acc0 = fmaf(sx[rg * D + k], w, acc0);
        acc1 = fmaf(sx[(rg + 4) * D + k], w, acc1);
    }
    g_h[(base + rg) * D + col] = acc0;
    g_h[(base + rg + 4) * D + col] = acc1;
}

// ---- launch 1: FUSED scan + CSR build + gather/pack (device phase sync) ----
// 512 blocks x 512 threads, __launch_bounds__(512,4): 4 blocks/SM guaranteed
// -> all 512 blocks resident -> spin-waits cannot deadlock.
__global__ void __launch_bounds__(BT, 4) k_build_gather() {
    int tid = threadIdx.x, blk = blockIdx.x;
    __shared__ int ssum[BT];

    // ---- phase A: block 0 scans degrees -> off/cur/dinv ----
    if (blk == 0) {
        int s = 0;
#pragma unroll
        for (int i = 0; i < 16; i++) s += (int)g_deg[tid * 16 + i];
        ssum[tid] = s;
        __syncthreads();
        for (int d = 1; d < BT; d <<= 1) {
            int x = (tid >= d) ? ssum[tid - d] : 0;
            __syncthreads();
            ssum[tid] += x;
            __syncthreads();
        }
        int run = ssum[tid] - s;   // exclusive prefix
#pragma unroll
        for (int i = 0; i < 16; i++) {
            int idx = tid * 16 + i;
            int v = (int)g_deg[idx];
            g_off[idx] = run;
            g_cur[idx] = run;
            g_dinv[idx] = rsqrtf((float)v + 1.0f);   // +1 self-loop
            run += v;
        }
        __syncthreads();
        if (tid == 0) { __threadfence(); g_scan_done = 1; }
    }
    if (tid == 0) { while (g_scan_done == 0) __nanosleep(64); }
    __syncthreads();
    __threadfence();

    // ---- phase B: CSR edge-id scatter (512 edges per block) ----
    {
        const void* ei = gp_ei;
        int E = g_E, ei32 = g_ei32;
        int e = blk * BT + tid;
        if (e < E && e < EMAX) {
            int src = fetch_idx(ei, e, ei32);
            int dst = fetch_idx(ei, E + e, ei32);
            if ((unsigned)dst < (unsigned)N_NODES) {
                if ((unsigned)src >= (unsigned)N_NODES) src = 0;
                int slot = atomicAdd(&g_cur[dst], 1);
                g_csr[slot] = src;
            }
        }
    }
    __threadfence();
    __syncthreads();
    if (tid == 0) {
        atomicAdd(&g_csr_done, 1);
        while (*(volatile int*)&g_csr_done < BB) __nanosleep(64);
    }
    __syncthreads();
    __threadfence();

    // ---- phase C: gather + self-term + bias + relu + fp16 pack (r13 form) ----
    const float* __restrict__ b = gp_b;
    int wid = tid >> 5, lane = tid & 31;
    int node = blk * 16 + wid;
    int off = g_off[node];
    int n = (int)g_deg[node];
    float dv = g_dinv[node];

    float2 a0 = make_float2(0.0f, 0.0f), a1 = make_float2(0.0f, 0.0f);
    int e = 0;
    for (; e + 1 < n; e += 2) {
        int s0 = g_csr[off + e], s1 = g_csr[off + e + 1];
        float d0 = g_dinv[s0], d1 = g_dinv[s1];
        float2 v0 = ((const float2*)(g_h + s0 * D))[lane];
        float2 v1 = ((const float2*)(g_h + s1 * D))[lane];
        a0.x = fmaf(d0, v0.x, a0.x); a0.y = fmaf(d0, v0.y, a0.y);
        a1.x = fmaf(d1, v1.x, a1.x); a1.y = fmaf(d1, v1.y, a1.y);
    }
    if (e < n) {
        int s0 = g_csr[off + e];
        float d0 = g_dinv[s0];
        float2 v0 = ((const float2*)(g_h + s0 * D))[lane];
        a0.x = fmaf(d0, v0.x, a0.x); a0.y = fmaf(d0, v0.y, a0.y);
    }
    float2 hv = ((const float2*)(g_h + node * D))[lane];
    float2 bb = ((const float2*)b)[lane];
    float ox = dv * (a0.x + a1.x + dv * hv.x) + bb.x;
    float oy = dv * (a0.y + a1.y + dv * hv.y) + bb.y;
    ox = ox > 0.0f ? ox : 0.0f;
    oy = oy > 0.0f ? oy : 0.0f;
    ((half2*)(g_P + node * D))[lane] = __floats2half2_rn(ox, oy);
}

// ---- launch 2: C = P @ P^T via mma.sync fp16, symmetric upper-tri tiles ----
#define PROW_BYTES 128
#define PTILE_BYTES (128 * PROW_BYTES)      // 16384
#define TSTRIDE 132
#define SMEM_TOTAL (128 * TSTRIDE * 4)       // 67584
#define CLEAN_CTAS 2016
#define CLEAN_WORDS N_NODES
#define WORDS_PER_CTA ((CLEAN_WORDS + CLEAN_CTAS - 1) / CLEAN_CTAS)

__device__ __forceinline__ uint32_t psw(int row, int chunk) {
    return (uint32_t)(row * PROW_BYTES + ((chunk ^ (row & 7)) << 4));
}

#define LDSM_X4(r0, r1, r2, r3, a) \
    asm volatile("ldmatrix.sync.aligned.m8n8.x4.shared.b16 {%0,%1,%2,%3}, [%4];" \
        : "=r"(r0), "=r"(r1), "=r"(r2), "=r"(r3) : "r"(a))

#define MMA_16816_F16(d, a, b) \
    asm volatile("mma.sync.aligned.m16n8k16.row.col.f32.f16.f16.f32 " \
        "{%0,%1,%2,%3}, {%4,%5,%6,%7}, {%8,%9}, {%0,%1,%2,%3};" \
        : "+f"((d)[0]), "+f"((d)[1]), "+f"((d)[2]), "+f"((d)[3]) \
        : "r"((a)[0]), "r"((a)[1]), "r"((a)[2]), "r"((a)[3]), "r"((b)[0]), "r"((b)[1]))

#define CP_ASYNC_16(smem_addr, gptr) \
    asm volatile("cp.async.cg.shared.global [%0], [%1], 16;" :: "r"(smem_addr), "l"(gptr) : "memory")

__global__ void __launch_bounds__(256, 2) k_gemm_mma(float* __restrict__ C) {
    int bi = blockIdx.y, bj = blockIdx.x;
    int tid = threadIdx.x;

    if (bj < bi) {
        // idle lower-triangle CTA: reset scratch for the next graph replay
        int cid = bi * (bi - 1) / 2 + bj;
        if (cid == 0 && tid == 0) { g_scan_done = 0; g_csr_done = 0; }
        int w0 = cid * WORDS_PER_CTA;
        for (int k = tid; k < WORDS_PER_CTA; k += 256) {
            int w = w0 + k;
            if (w < CLEAN_WORDS) g_deg[w] = 0.0f;
        }
        return;
    }

    extern __shared__ char smem[];
    char* sA = smem;
    char* sB = smem + PTILE_BYTES;
    uint32_t sA_u = smem_u32(sA);
    uint32_t sB_u = smem_u32(sB);

    int wid = tid >> 5, lane = tid & 31;
    int warp_m = wid >> 1;
    int warp_n = wid & 1;

    const char* gA = (const char*)(g_P + bi * 128 * D);
    const char* gB = (const char*)(g_P + bj * 128 * D);

#pragma unroll
    for (int it = 0; it < 4; it++) {
        int q = it * 256 + tid;
        int row = q >> 3, chunk = q & 7;
        uint32_t off = psw(row, chunk);
        CP_ASYNC_16(sA_u + off, gA + q * 16);
        CP_ASYNC_16(sB_u + off, gB + q * 16);
    }
    asm volatile("cp.async.commit_group;" ::: "memory");
    asm volatile("cp.async.wait_group 0;" ::: "memory");
    __syncthreads();

    int a_row_in16 = (lane & 7) | (lane & 8);
    int a_csub = lane >> 4;
    int b_row_in16 = (lane & 7) | ((lane >> 1) & 8);
    int b_csub = (lane >> 3) & 1;
    int a_row0 = warp_m * 32 + a_row_in16;
    int b_row0 = warp_n * 64 + b_row_in16;

    float acc[2][8][4];
#pragma unroll
    for (int mi = 0; mi < 2; mi++)
#pragma unroll
        for (int ni = 0; ni < 8; ni++)
#pragma unroll
            for (int v = 0; v < 4; v++) acc[mi][ni][v] = 0.0f;

#pragma unroll
    for (int s = 0; s < 4; s++) {
        int kc = s * 2;

        uint32_t a[2][4];
#pragma unroll
        for (int mi = 0; mi < 2; mi++)
            LDSM_X4(a[mi][0], a[mi][1], a[mi][2], a[mi][3],
                    sA_u + psw(a_row0 + mi * 16, kc + a_csub));

        uint32_t b[4][4];
#pragma unroll
        for (int nt = 0; nt < 4; nt++)
            LDSM_X4(b[nt][0], b[nt][1], b[nt][2], b[nt][3],
                    sB_u + psw(b_row0 + nt * 16, kc + b_csub));

#pragma unroll
        for (int mi = 0; mi < 2; mi++)
#pragma unroll
            for (int ni = 0; ni < 8; ni++) {
                uint32_t bb[2];
                bb[0] = b[ni >> 1][(ni & 1) * 2];
                bb[1] = b[ni >> 1][(ni & 1) * 2 + 1];
                MMA_16816_F16(acc[mi][ni], a[mi], bb);
            }
    }

    int gr = lane >> 2, gc = (lane & 3) * 2;
    float* sS = (float*)smem;

    // ---- epilogue 1: staged store of C[bi, bj], single pass ----
    __syncthreads();
#pragma unroll
    for (int mi = 0; mi < 2; mi++) {
#pragma unroll
        for (int ni = 0; ni < 8; ni++) {
            int lr = warp_m * 32 + mi * 16 + gr;
            int lc = warp_n * 64 + ni * 8 + gc;
            sS[lr * TSTRIDE + lc]           = acc[mi][ni][0];
            sS[lr * TSTRIDE + lc + 1]       = acc[mi][ni][1];
            sS[(lr + 8) * TSTRIDE + lc]     = acc[mi][ni][2];
            sS[(lr + 8) * TSTRIDE + lc + 1] = acc[mi][ni][3];
        }
    }
    __syncthreads();
#pragma unroll
    for (int k = 0; k < 16; k++) {
        int f = k * 256 + tid;
        int row = f >> 5, c4 = f & 31;
        float4 v = *(const float4*)(sS + row * TSTRIDE + c4 * 4);
        *(float4*)(C + (long long)(bi * 128 + row) * NT + bj * 128 + c4 * 4) = v;
    }

    // ---- epilogue 2: transposed store of C[bj, bi], single pass ----
    if (bi == bj) return;
    __syncthreads();
#pragma unroll
    for (int mi = 0; mi < 2; mi++) {
#pragma unroll
        for (int ni = 0; ni < 8; ni++) {
            int lr = warp_m * 32 + mi * 16 + gr;
            int lc = warp_n * 64 + ni * 8 + gc;
            sS[lc * TSTRIDE + lr]           = acc[mi][ni][0];
            sS[(lc + 1) * TSTRIDE + lr]     = acc[mi][ni][1];
            sS[lc * TSTRIDE + lr + 8]       = acc[mi][ni][2];
            sS[(lc + 1) * TSTRIDE + lr + 8] = acc[mi][ni][3];
        }
    }
    __syncthreads();
#pragma unroll
    for (int k = 0; k < 16; k++) {
        int f = k * 256 + tid;
        int row = f >> 5, c4 = f & 31;
        float4 v = *(const float4*)(sS + row * TSTRIDE + c4 * 4);
        *(float4*)(C + (long long)(bj * 128 + row) * NT + bi * 128 + c4 * 4) = v;
    }
}

extern "C" void kernel_launch(void* const* d_in, const int* in_sizes, int n_in,
                              void* d_out, int out_size) {
    float* out = (float*)d_out;

    const void* p0 = n_in > 0 ? d_in[0] : nullptr;
    const void* p1 = n_in > 1 ? d_in[1] : nullptr;
    const void* p2 = n_in > 2 ? d_in[2] : nullptr;
    const void* p3 = n_in > 3 ? d_in[3] : nullptr;
    int s0 = n_in > 0 ? in_sizes[0] : 0;
    int s1 = n_in > 1 ? in_sizes[1] : 0;
    int s2 = n_in > 2 ? in_sizes[2] : 0;
    int s3 = n_in > 3 ? in_sizes[3] : 0;

    static bool attr_set = false;
    if (!attr_set) {
        cudaFuncSetAttribute(k_gemm_mma, cudaFuncAttributeMaxDynamicSharedMemorySize, SMEM_TOTAL);
        attr_set = true;
    }

    // launch 0: classify/publish + degree histogram (1024) + x@W (1024)
    k_deg_xw<<<2048, 256>>>(p0, p1, p2, p3, s0, s1, s2, s3);
    // launch 1: fused scan + CSR build + gather/pack
    k_build_gather<<<BB, BT>>>();
    // launch 2: GEMM
    dim3 grid(NT / 128, NT / 128);
    k_gemm_mma<<<grid, 256, SMEM_TOTAL>>>(out);
}